// round 11
// baseline (speedup 1.0000x reference)
#include <cuda_runtime.h>
#include <math.h>

#define H      128
#define H3     384
#define HALF   64
#define BATCH  64
#define TT     2048
#define TILE   128   // time steps staged per smem chunk

typedef unsigned long long ull_t;

// feat[b*256 + dir*128 + i] = mean over t of hidden state
__device__ float g_feat[BATCH * 2 * H];

__device__ __forceinline__ ull_t pack2(float lo, float hi) {
    return (ull_t)__float_as_uint(lo) | ((ull_t)__float_as_uint(hi) << 32);
}
__device__ __forceinline__ float lo2(ull_t v) { return __uint_as_float((unsigned)v); }
__device__ __forceinline__ float hi2(ull_t v) { return __uint_as_float((unsigned)(v >> 32)); }

__device__ __forceinline__ ull_t ffma2(ull_t a, ull_t b, ull_t c) {
    ull_t d;
    asm("fma.rn.f32x2 %0, %1, %2, %3;" : "=l"(d) : "l"(a), "l"(b), "l"(c));
    return d;
}
__device__ __forceinline__ float ex2f(float x) {
    float r; asm("ex2.approx.ftz.f32 %0, %1;" : "=f"(r) : "f"(x)); return r;
}
__device__ __forceinline__ float rcpf(float x) {
    float r; asm("rcp.approx.ftz.f32 %0, %1;" : "=f"(r) : "f"(x)); return r;
}
__device__ __forceinline__ float tanhf_hw(float x) {
    float r; asm("tanh.approx.f32 %0, %1;" : "=f"(r) : "f"(x)); return r;
}

#define L2E 1.4426950408889634f

// gate sigmoid via HW tanh: sig(x) = 0.5*tanh(0.5x) + 0.5
__device__ __forceinline__ float fsig_hw(float x) {
    return fmaf(0.5f, tanhf_hw(0.5f * x), 0.5f);
}
__device__ __forceinline__ float ftanh(float x) {   // accurate path (MLP)
    return 2.0f * rcpf(1.0f + ex2f(-2.0f * L2E * x)) - 1.0f;
}

// dummy kernel so ncu (-s 5 -c 1) lands on the GRU kernel
__global__ void nop_kernel() {}

// One persistent block per (batch, direction). 256 threads.
// Thread t: unit i = t & 127, k-half = t >> 7.
//   half 0 (warps 0-3): updaters — combine partials, gates, h update.
//   half 1 (warps 4-7): partials (with xw FOLDED IN) + next-step xw in regs.
// Barrier protocol (2 barrier ops per step on each path):
//   bar1 (256): h1 arrive after part STS; upd sync before phase 2.
//   bar3 (256): joint sync — publishes h, orders everything else.
//   bar4 (128): h1-only — yu_s chunk staging.
// part_s[i] = (pr'+xwr, pz'+xwz, pn', xwn)  [xwn separate: outside r-mult]
__global__ void __launch_bounds__(256, 1) gru_persist_kernel(
    const float* __restrict__ y, const float* __restrict__ u,
    const float* __restrict__ Wi_f, const float* __restrict__ bi_f,
    const float* __restrict__ Wh_f, const float* __restrict__ bhn_f,
    const float* __restrict__ Wi_b, const float* __restrict__ bi_b,
    const float* __restrict__ Wh_b, const float* __restrict__ bhn_b)
{
    const int blk  = blockIdx.x;        // 0..127
    const int b    = blk & (BATCH - 1);
    const int dir  = blk >> 6;          // 0 = fwd, 1 = bwd
    const int t    = threadIdx.x;       // 0..255
    const int i    = t & (H - 1);       // unit 0..127
    const int half = t >> 7;            // k-half
    const int k0   = half * HALF;
    const bool upd = (t < H);           // warps 0-3

    const float* Wi  = dir ? Wi_b  : Wi_f;
    const float* bi  = dir ? bi_b  : bi_f;
    const float* Wh  = dir ? Wh_b  : Wh_f;
    const float* bhn = dir ? bhn_b : bhn_f;

    // ---- register-resident recurrent weights: 3 gates x half-k, packed ----
    ull_t wr[HALF / 2], wz[HALF / 2], wn[HALF / 2];
#pragma unroll
    for (int m = 0; m < HALF / 2; ++m) {
        const float* r0 = Wh + (size_t)(k0 + 2 * m)     * H3;
        const float* r1 = Wh + (size_t)(k0 + 2 * m + 1) * H3;
        wr[m] = pack2(r0[i],         r1[i]);
        wz[m] = pack2(r0[i + H],     r1[i + H]);
        wn[m] = pack2(r0[i + 2 * H], r1[i + 2 * H]);
    }

    // ---- shared state ----
    __shared__ __align__(16) float  h_s[H];
    __shared__ __align__(16) float4 part_s[H];        // from half 1
    __shared__ __align__(16) float4 yu_s[TILE * 2];   // per step: y(4)+u(4)
    __shared__ __align__(16) float4 wi4_s[2 * H3];    // Wi columns, 2 float4 each

    for (int col = t; col < H3; col += 256) {
        wi4_s[col]      = make_float4(Wi[0 * H3 + col], Wi[1 * H3 + col],
                                      Wi[2 * H3 + col], Wi[3 * H3 + col]);
        wi4_s[H3 + col] = make_float4(Wi[4 * H3 + col], Wi[5 * H3 + col],
                                      Wi[6 * H3 + col], Wi[7 * H3 + col]);
    }

    float bhn_i = 0.0f, bir = 0.0f, biz = 0.0f, bin = 0.0f;
    if (upd) {
        bhn_i = bhn[i];
    } else {
        bir = bi[i]; biz = bi[i + H]; bin = bi[i + 2 * H];
    }

    if (t < H) h_s[t] = 0.0f;
    __syncthreads();

    float hsum = 0.0f;                  // updaters only
    float xwr = 0.0f, xwz = 0.0f, xwn = 0.0f;   // h1: xw of current step

    // h1: preload chunk 0 inputs into regs
    float4 y4n = make_float4(0, 0, 0, 0), u4n = y4n;
    if (!upd) {
        const int tc0 = (dir ? (TT - TILE) : 0) + i;
        y4n = *(const float4*)(y + ((size_t)b * TT + tc0) * 4);
        u4n = *(const float4*)(u + ((size_t)b * TT + tc0) * 4);
    }

    const int nchunk = TT / TILE;
    for (int c = 0; c < nchunk; ++c) {
        const int tt0 = dir ? (TILE - 1) : 0;
        const int sgn = dir ? -1 : 1;

        if (!upd) {
            // stage current chunk from regs; prefetch next chunk
            yu_s[2 * i]     = y4n;
            yu_s[2 * i + 1] = u4n;
            asm volatile("bar.sync 4, 128;" ::: "memory");   // h1-only
            if (c + 1 < nchunk) {
                const int t0n = dir ? (TT - (c + 2) * TILE) : ((c + 1) * TILE);
                y4n = *(const float4*)(y + ((size_t)b * TT + t0n + i) * 4);
                u4n = *(const float4*)(u + ((size_t)b * TT + t0n + i) * 4);
            }
            // xw for step 0 of this chunk (regs)
            const float4 ya = yu_s[2 * tt0];
            const float4 ub = yu_s[2 * tt0 + 1];
            const float4 war = wi4_s[i],          wbr = wi4_s[H3 + i];
            const float4 waz = wi4_s[i + H],      wbz = wi4_s[H3 + i + H];
            const float4 wan = wi4_s[i + 2 * H],  wbn = wi4_s[H3 + i + 2 * H];
            float xr = bir, xz = biz, xn = bin;
            xr = fmaf(ya.x, war.x, xr); xr = fmaf(ya.y, war.y, xr);
            xr = fmaf(ya.z, war.z, xr); xr = fmaf(ya.w, war.w, xr);
            xr = fmaf(ub.x, wbr.x, xr); xr = fmaf(ub.y, wbr.y, xr);
            xr = fmaf(ub.z, wbr.z, xr); xr = fmaf(ub.w, wbr.w, xr);
            xz = fmaf(ya.x, waz.x, xz); xz = fmaf(ya.y, waz.y, xz);
            xz = fmaf(ya.z, waz.z, xz); xz = fmaf(ya.w, waz.w, xz);
            xz = fmaf(ub.x, wbz.x, xz); xz = fmaf(ub.y, wbz.y, xz);
            xz = fmaf(ub.z, wbz.z, xz); xz = fmaf(ub.w, wbz.w, xz);
            xn = fmaf(ya.x, wan.x, xn); xn = fmaf(ya.y, wan.y, xn);
            xn = fmaf(ya.z, wan.z, xn); xn = fmaf(ya.w, wan.w, xn);
            xn = fmaf(ub.x, wbn.x, xn); xn = fmaf(ub.y, wbn.y, xn);
            xn = fmaf(ub.z, wbn.z, xn); xn = fmaf(ub.w, wbn.w, xn);
            xwr = xr; xwz = xz; xwn = xn;
        }

        for (int s = 0; s < TILE; ++s) {
            // ---- phase 1: 3 partial dots over h[k0:k0+64] (all threads) ----
            const ulonglong2* h2 = (const ulonglong2*)(h_s + k0);
            ull_t ar = 0ull, az = 0ull, an = 0ull;
#pragma unroll
            for (int m = 0; m < HALF / 4; ++m) {
                const ulonglong2 hv = h2[m];   // broadcast; shared 3 ways
                ar = ffma2(hv.x, wr[2 * m],     ar);
                az = ffma2(hv.x, wz[2 * m],     az);
                an = ffma2(hv.x, wn[2 * m],     an);
                ar = ffma2(hv.y, wr[2 * m + 1], ar);
                az = ffma2(hv.y, wz[2 * m + 1], az);
                an = ffma2(hv.y, wn[2 * m + 1], an);
            }
            const float pr = lo2(ar) + hi2(ar);
            const float pz = lo2(az) + hi2(az);
            const float pn = lo2(an) + hi2(an);

            if (upd) {
                const float hold = h_s[i];               // pre-bar issue
                asm volatile("bar.sync 1, 256;" ::: "memory");  // part_s ready
                // ---- phase 2 ----
                const float4 p = part_s[i];
                const float r = fsig_hw(pr + p.x);       // p.x has xwr folded
                const float z = fsig_hw(pz + p.y);       // p.y has xwz folded
                const float pn_full = (pn + p.z) + bhn_i;
                const float arg = fmaf(r, pn_full, p.w); // p.w = xwn
                const float n   = tanhf_hw(arg);
                const float hn  = fmaf(z, hold - n, n);  // (1-z)n + z h
                h_s[i] = hn;
                hsum += hn;
            } else {
                part_s[i] = make_float4(pr + xwr, pz + xwz, pn, xwn);
                asm volatile("bar.arrive 1, 256;" ::: "memory"); // release upd
                // next step's xw into regs (overlaps updaters' phase 2)
                if (s + 1 < TILE) {
                    const int tt_n = tt0 + sgn * (s + 1);
                    const float4 ya = yu_s[2 * tt_n];
                    const float4 ub = yu_s[2 * tt_n + 1];
                    const float4 war = wi4_s[i],         wbr = wi4_s[H3 + i];
                    const float4 waz = wi4_s[i + H],     wbz = wi4_s[H3 + i + H];
                    const float4 wan = wi4_s[i + 2 * H], wbn = wi4_s[H3 + i + 2 * H];
                    float xr = bir, xz = biz, xn = bin;
                    xr = fmaf(ya.x, war.x, xr); xr = fmaf(ya.y, war.y, xr);
                    xr = fmaf(ya.z, war.z, xr); xr = fmaf(ya.w, war.w, xr);
                    xr = fmaf(ub.x, wbr.x, xr); xr = fmaf(ub.y, wbr.y, xr);
                    xr = fmaf(ub.z, wbr.z, xr); xr = fmaf(ub.w, wbr.w, xr);
                    xz = fmaf(ya.x, waz.x, xz); xz = fmaf(ya.y, waz.y, xz);
                    xz = fmaf(ya.z, waz.z, xz); xz = fmaf(ya.w, waz.w, xz);
                    xz = fmaf(ub.x, wbz.x, xz); xz = fmaf(ub.y, wbz.y, xz);
                    xz = fmaf(ub.z, wbz.z, xz); xz = fmaf(ub.w, wbz.w, xz);
                    xn = fmaf(ya.x, wan.x, xn); xn = fmaf(ya.y, wan.y, xn);
                    xn = fmaf(ya.z, wan.z, xn); xn = fmaf(ya.w, wan.w, xn);
                    xn = fmaf(ub.x, wbn.x, xn); xn = fmaf(ub.y, wbn.y, xn);
                    xn = fmaf(ub.z, wbn.z, xn); xn = fmaf(ub.w, wbn.w, xn);
                    xwr = xr; xwz = xz; xwn = xn;
                }
            }
            // joint sync: publishes h, orders part_s WAR, everything
            asm volatile("bar.sync 3, 256;" ::: "memory");
        }
    }

    if (upd)
        g_feat[b * (2 * H) + dir * H + i] = hsum * (1.0f / (float)TT);
}

// MLP heads: 256 -> 128 -> 64 -> 20, tanh, tanh, linear. (accurate tanh)
__global__ void __launch_bounds__(128) mlp_kernel(
    const float* __restrict__ mW0, const float* __restrict__ mb0,
    const float* __restrict__ mW1, const float* __restrict__ mb1,
    const float* __restrict__ mW2, const float* __restrict__ mb2,
    const float* __restrict__ sW0, const float* __restrict__ sb0,
    const float* __restrict__ sW1, const float* __restrict__ sb1,
    const float* __restrict__ sW2, const float* __restrict__ sb2,
    float* __restrict__ out)
{
    const int b    = blockIdx.x & (BATCH - 1);
    const int head = blockIdx.x >> 6;
    const int j    = threadIdx.x;

    const float* W0 = head ? sW0 : mW0;
    const float* b0 = head ? sb0 : mb0;
    const float* W1 = head ? sW1 : mW1;
    const float* b1 = head ? sb1 : mb1;
    const float* W2 = head ? sW2 : mW2;
    const float* b2 = head ? sb2 : mb2;

    __shared__ float feat_s[256];
    __shared__ float h1_s[128];
    __shared__ float h2_s[64];

    feat_s[j]       = g_feat[b * 256 + j];
    feat_s[j + 128] = g_feat[b * 256 + j + 128];
    __syncthreads();

    {   // layer 0: 256 -> 128
        float acc = b0[j];
#pragma unroll 8
        for (int i = 0; i < 256; ++i)
            acc = fmaf(feat_s[i], __ldg(W0 + (size_t)i * 128 + j), acc);
        h1_s[j] = ftanh(acc);
    }
    __syncthreads();

    if (j < 64) {   // layer 1: 128 -> 64
        float acc = b1[j];
#pragma unroll 8
        for (int i = 0; i < 128; ++i)
            acc = fmaf(h1_s[i], __ldg(W1 + (size_t)i * 64 + j), acc);
        h2_s[j] = ftanh(acc);
    }
    __syncthreads();

    if (j < 20) {   // layer 2: 64 -> 20
        float acc = b2[j];
#pragma unroll
        for (int i = 0; i < 64; ++i)
            acc = fmaf(h2_s[i], __ldg(W2 + (size_t)i * 20 + j), acc);
        out[head * (BATCH * 20) + b * 20 + j] = acc;
    }
}

extern "C" void kernel_launch(void* const* d_in, const int* in_sizes, int n_in,
                              void* d_out, int out_size)
{
    const float* y     = (const float*)d_in[0];
    const float* u     = (const float*)d_in[1];
    const float* Wi_f  = (const float*)d_in[2];
    const float* bi_f  = (const float*)d_in[3];
    const float* Wh_f  = (const float*)d_in[4];
    const float* bhn_f = (const float*)d_in[5];
    const float* Wi_b  = (const float*)d_in[6];
    const float* bi_b  = (const float*)d_in[7];
    const float* Wh_b  = (const float*)d_in[8];
    const float* bhn_b = (const float*)d_in[9];
    const float* mW0   = (const float*)d_in[10];
    const float* mb0   = (const float*)d_in[11];
    const float* mW1   = (const float*)d_in[12];
    const float* mb1   = (const float*)d_in[13];
    const float* mW2   = (const float*)d_in[14];
    const float* mb2   = (const float*)d_in[15];
    const float* sW0   = (const float*)d_in[16];
    const float* sb0   = (const float*)d_in[17];
    const float* sW1   = (const float*)d_in[18];
    const float* sb1   = (const float*)d_in[19];
    const float* sW2   = (const float*)d_in[20];
    const float* sb2   = (const float*)d_in[21];

    nop_kernel<<<1, 32>>>();
    gru_persist_kernel<<<BATCH * 2, 256>>>(y, u, Wi_f, bi_f, Wh_f, bhn_f,
                                           Wi_b, bi_b, Wh_b, bhn_b);
    nop_kernel<<<1, 32>>>();
    mlp_kernel<<<BATCH * 2, 128>>>(mW0, mb0, mW1, mb1, mW2, mb2,
                                   sW0, sb0, sW1, sb1, sW2, sb2,
                                   (float*)d_out);
}

// round 12
// speedup vs baseline: 1.0324x; 1.0324x over previous
#include <cuda_runtime.h>
#include <math.h>

#define H      128
#define H3     384
#define HALF   64
#define BATCH  64
#define TT     2048
#define TILE   128   // time steps staged per smem chunk

typedef unsigned long long ull_t;

// feat[b*256 + dir*128 + i] = mean over t of hidden state
__device__ float g_feat[BATCH * 2 * H];

__device__ __forceinline__ ull_t pack2(float lo, float hi) {
    return (ull_t)__float_as_uint(lo) | ((ull_t)__float_as_uint(hi) << 32);
}
__device__ __forceinline__ float lo2(ull_t v) { return __uint_as_float((unsigned)v); }
__device__ __forceinline__ float hi2(ull_t v) { return __uint_as_float((unsigned)(v >> 32)); }

__device__ __forceinline__ ull_t ffma2(ull_t a, ull_t b, ull_t c) {
    ull_t d;
    asm("fma.rn.f32x2 %0, %1, %2, %3;" : "=l"(d) : "l"(a), "l"(b), "l"(c));
    return d;
}
__device__ __forceinline__ float ex2f(float x) {
    float r; asm("ex2.approx.ftz.f32 %0, %1;" : "=f"(r) : "f"(x)); return r;
}
__device__ __forceinline__ float rcpf(float x) {
    float r; asm("rcp.approx.ftz.f32 %0, %1;" : "=f"(r) : "f"(x)); return r;
}
__device__ __forceinline__ float tanhf_hw(float x) {
    float r; asm("tanh.approx.f32 %0, %1;" : "=f"(r) : "f"(x)); return r;
}

#define L2E 1.4426950408889634f

// gate sigmoid via HW tanh: sig(x) = 0.5*tanh(0.5x) + 0.5
__device__ __forceinline__ float fsig_hw(float x) {
    return fmaf(0.5f, tanhf_hw(0.5f * x), 0.5f);
}
__device__ __forceinline__ float ftanh(float x) {   // accurate path (MLP)
    return 2.0f * rcpf(1.0f + ex2f(-2.0f * L2E * x)) - 1.0f;
}

// One persistent block per (batch, direction). 256 threads.
// Thread t: unit i = t & 127, k-half = t >> 7.
//   half 0 (warps 0-3): updaters — combine partials, gates, h update.
//   half 1 (warps 4-7): partials (xw folded in) + next-step xw in regs.
// Barrier protocol (R10-proven):
//   bar1 (256): h1 arrive after part STS; upd sync before phase 2.
//   bar3 (256): upd arrive after h STS;  h1 sync before next dot.
//   bar2 (128): upd-only sync — orders h writes among updaters.
//   bar4 (128): h1-only — yu_s chunk staging.
// part_s[i] = (pr'+xwr, pz'+xwz, pn', xwn)
__global__ void __launch_bounds__(256, 1) gru_persist_kernel(
    const float* __restrict__ y, const float* __restrict__ u,
    const float* __restrict__ Wi_f, const float* __restrict__ bi_f,
    const float* __restrict__ Wh_f, const float* __restrict__ bhn_f,
    const float* __restrict__ Wi_b, const float* __restrict__ bi_b,
    const float* __restrict__ Wh_b, const float* __restrict__ bhn_b)
{
    const int blk  = blockIdx.x;        // 0..127
    const int b    = blk & (BATCH - 1);
    const int dir  = blk >> 6;          // 0 = fwd, 1 = bwd
    const int t    = threadIdx.x;       // 0..255
    const int i    = t & (H - 1);       // unit 0..127
    const int half = t >> 7;            // k-half
    const int k0   = half * HALF;
    const bool upd = (t < H);           // warps 0-3

    const float* Wi  = dir ? Wi_b  : Wi_f;
    const float* bi  = dir ? bi_b  : bi_f;
    const float* Wh  = dir ? Wh_b  : Wh_f;
    const float* bhn = dir ? bhn_b : bhn_f;

    // ---- register-resident recurrent weights: 3 gates x half-k, packed ----
    ull_t wr[HALF / 2], wz[HALF / 2], wn[HALF / 2];
#pragma unroll
    for (int m = 0; m < HALF / 2; ++m) {
        const float* r0 = Wh + (size_t)(k0 + 2 * m)     * H3;
        const float* r1 = Wh + (size_t)(k0 + 2 * m + 1) * H3;
        wr[m] = pack2(r0[i],         r1[i]);
        wz[m] = pack2(r0[i + H],     r1[i + H]);
        wn[m] = pack2(r0[i + 2 * H], r1[i + 2 * H]);
    }

    // ---- shared state ----
    __shared__ __align__(16) float  h_s[H];
    __shared__ __align__(16) float4 part_s[H];        // from half 1
    __shared__ __align__(16) float4 yu_s[TILE * 2];   // per step: y(4)+u(4)
    __shared__ __align__(16) float4 wi4_s[2 * H3];    // Wi columns, 2 float4 each

    for (int col = t; col < H3; col += 256) {
        wi4_s[col]      = make_float4(Wi[0 * H3 + col], Wi[1 * H3 + col],
                                      Wi[2 * H3 + col], Wi[3 * H3 + col]);
        wi4_s[H3 + col] = make_float4(Wi[4 * H3 + col], Wi[5 * H3 + col],
                                      Wi[6 * H3 + col], Wi[7 * H3 + col]);
    }

    float bhn_i = 0.0f, bir = 0.0f, biz = 0.0f, bin = 0.0f;
    if (upd) {
        bhn_i = bhn[i];
    } else {
        bir = bi[i]; biz = bi[i + H]; bin = bi[i + 2 * H];
    }

    if (t < H) h_s[t] = 0.0f;
    __syncthreads();

    float hsum = 0.0f;                  // updaters only
    float xwr = 0.0f, xwz = 0.0f, xwn = 0.0f;   // h1: xw of current step

    // h1: preload chunk 0 inputs into regs
    float4 y4n = make_float4(0, 0, 0, 0), u4n = y4n;
    if (!upd) {
        const int tc0 = (dir ? (TT - TILE) : 0) + i;
        y4n = *(const float4*)(y + ((size_t)b * TT + tc0) * 4);
        u4n = *(const float4*)(u + ((size_t)b * TT + tc0) * 4);
    }

    const int nchunk = TT / TILE;
    for (int c = 0; c < nchunk; ++c) {
        const int tt0 = dir ? (TILE - 1) : 0;
        const int sgn = dir ? -1 : 1;

        if (!upd) {
            // stage current chunk from regs; prefetch next chunk
            yu_s[2 * i]     = y4n;
            yu_s[2 * i + 1] = u4n;
            asm volatile("bar.sync 4, 128;" ::: "memory");   // h1-only
            if (c + 1 < nchunk) {
                const int t0n = dir ? (TT - (c + 2) * TILE) : ((c + 1) * TILE);
                y4n = *(const float4*)(y + ((size_t)b * TT + t0n + i) * 4);
                u4n = *(const float4*)(u + ((size_t)b * TT + t0n + i) * 4);
            }
            // xw for step 0 of this chunk (regs)
            const float4 ya = yu_s[2 * tt0];
            const float4 ub = yu_s[2 * tt0 + 1];
            const float4 war = wi4_s[i],          wbr = wi4_s[H3 + i];
            const float4 waz = wi4_s[i + H],      wbz = wi4_s[H3 + i + H];
            const float4 wan = wi4_s[i + 2 * H],  wbn = wi4_s[H3 + i + 2 * H];
            float xr = bir, xz = biz, xn = bin;
            xr = fmaf(ya.x, war.x, xr); xr = fmaf(ya.y, war.y, xr);
            xr = fmaf(ya.z, war.z, xr); xr = fmaf(ya.w, war.w, xr);
            xr = fmaf(ub.x, wbr.x, xr); xr = fmaf(ub.y, wbr.y, xr);
            xr = fmaf(ub.z, wbr.z, xr); xr = fmaf(ub.w, wbr.w, xr);
            xz = fmaf(ya.x, waz.x, xz); xz = fmaf(ya.y, waz.y, xz);
            xz = fmaf(ya.z, waz.z, xz); xz = fmaf(ya.w, waz.w, xz);
            xz = fmaf(ub.x, wbz.x, xz); xz = fmaf(ub.y, wbz.y, xz);
            xz = fmaf(ub.z, wbz.z, xz); xz = fmaf(ub.w, wbz.w, xz);
            xn = fmaf(ya.x, wan.x, xn); xn = fmaf(ya.y, wan.y, xn);
            xn = fmaf(ya.z, wan.z, xn); xn = fmaf(ya.w, wan.w, xn);
            xn = fmaf(ub.x, wbn.x, xn); xn = fmaf(ub.y, wbn.y, xn);
            xn = fmaf(ub.z, wbn.z, xn); xn = fmaf(ub.w, wbn.w, xn);
            xwr = xr; xwz = xz; xwn = xn;
        }

        for (int s = 0; s < TILE; ++s) {
            // ---- phase 1: 3 partial dots over h[k0:k0+64] (all threads) ----
            const ulonglong2* h2 = (const ulonglong2*)(h_s + k0);
            ull_t ar = 0ull, az = 0ull, an = 0ull;
#pragma unroll
            for (int m = 0; m < HALF / 4; ++m) {
                const ulonglong2 hv = h2[m];   // broadcast; shared 3 ways
                ar = ffma2(hv.x, wr[2 * m],     ar);
                az = ffma2(hv.x, wz[2 * m],     az);
                an = ffma2(hv.x, wn[2 * m],     an);
                ar = ffma2(hv.y, wr[2 * m + 1], ar);
                az = ffma2(hv.y, wz[2 * m + 1], az);
                an = ffma2(hv.y, wn[2 * m + 1], an);
            }
            const float pr = lo2(ar) + hi2(ar);
            const float pz = lo2(az) + hi2(az);
            const float pn = lo2(an) + hi2(an);

            if (upd) {
                const float hold = h_s[i];               // pre-bar issue
                asm volatile("bar.sync 1, 256;" ::: "memory");  // part_s ready
                // ---- phase 2 (r-fold: one less dependent FMA) ----
                const float4 p = part_s[i];
                const float th = tanhf_hw(0.5f * (pr + p.x));  // r = .5th+.5
                const float z  = fsig_hw(pz + p.y);
                const float P  = (pn + p.z) + bhn_i;           // n recur part
                const float hP = 0.5f * P;                     // parallel
                const float bs = hP + p.w;                     // hP + xwn
                const float arg = fmaf(th, hP, bs);            // = xwn + r*P
                const float n   = tanhf_hw(arg);
                const float hn  = fmaf(z, hold - n, n);        // (1-z)n + z h
                h_s[i] = hn;
                hsum += hn;
                asm volatile("bar.arrive 3, 256;" ::: "memory"); // h published
                asm volatile("bar.sync 2, 128;"   ::: "memory"); // upd-internal
            } else {
                part_s[i] = make_float4(pr + xwr, pz + xwz, pn, xwn);
                asm volatile("bar.arrive 1, 256;" ::: "memory"); // release upd
                // next step's xw into regs (overlaps updaters' phase 2)
                if (s + 1 < TILE) {
                    const int tt_n = tt0 + sgn * (s + 1);
                    const float4 ya = yu_s[2 * tt_n];
                    const float4 ub = yu_s[2 * tt_n + 1];
                    const float4 war = wi4_s[i],         wbr = wi4_s[H3 + i];
                    const float4 waz = wi4_s[i + H],     wbz = wi4_s[H3 + i + H];
                    const float4 wan = wi4_s[i + 2 * H], wbn = wi4_s[H3 + i + 2 * H];
                    float xr = bir, xz = biz, xn = bin;
                    xr = fmaf(ya.x, war.x, xr); xr = fmaf(ya.y, war.y, xr);
                    xr = fmaf(ya.z, war.z, xr); xr = fmaf(ya.w, war.w, xr);
                    xr = fmaf(ub.x, wbr.x, xr); xr = fmaf(ub.y, wbr.y, xr);
                    xr = fmaf(ub.z, wbr.z, xr); xr = fmaf(ub.w, wbr.w, xr);
                    xz = fmaf(ya.x, waz.x, xz); xz = fmaf(ya.y, waz.y, xz);
                    xz = fmaf(ya.z, waz.z, xz); xz = fmaf(ya.w, waz.w, xz);
                    xz = fmaf(ub.x, wbz.x, xz); xz = fmaf(ub.y, wbz.y, xz);
                    xz = fmaf(ub.z, wbz.z, xz); xz = fmaf(ub.w, wbz.w, xz);
                    xn = fmaf(ya.x, wan.x, xn); xn = fmaf(ya.y, wan.y, xn);
                    xn = fmaf(ya.z, wan.z, xn); xn = fmaf(ya.w, wan.w, xn);
                    xn = fmaf(ub.x, wbn.x, xn); xn = fmaf(ub.y, wbn.y, xn);
                    xn = fmaf(ub.z, wbn.z, xn); xn = fmaf(ub.w, wbn.w, xn);
                    xwr = xr; xwz = xz; xwn = xn;
                }
                asm volatile("bar.sync 3, 256;" ::: "memory");   // wait for h
            }
        }
    }

    if (upd)
        g_feat[b * (2 * H) + dir * H + i] = hsum * (1.0f / (float)TT);
}

// MLP heads: 256 -> 128 -> 64 -> 20, tanh, tanh, linear. (accurate tanh)
__global__ void __launch_bounds__(128) mlp_kernel(
    const float* __restrict__ mW0, const float* __restrict__ mb0,
    const float* __restrict__ mW1, const float* __restrict__ mb1,
    const float* __restrict__ mW2, const float* __restrict__ mb2,
    const float* __restrict__ sW0, const float* __restrict__ sb0,
    const float* __restrict__ sW1, const float* __restrict__ sb1,
    const float* __restrict__ sW2, const float* __restrict__ sb2,
    float* __restrict__ out)
{
    const int b    = blockIdx.x & (BATCH - 1);
    const int head = blockIdx.x >> 6;
    const int j    = threadIdx.x;

    const float* W0 = head ? sW0 : mW0;
    const float* b0 = head ? sb0 : mb0;
    const float* W1 = head ? sW1 : mW1;
    const float* b1 = head ? sb1 : mb1;
    const float* W2 = head ? sW2 : mW2;
    const float* b2 = head ? sb2 : mb2;

    __shared__ float feat_s[256];
    __shared__ float h1_s[128];
    __shared__ float h2_s[64];

    feat_s[j]       = g_feat[b * 256 + j];
    feat_s[j + 128] = g_feat[b * 256 + j + 128];
    __syncthreads();

    {   // layer 0: 256 -> 128
        float acc = b0[j];
#pragma unroll 8
        for (int i = 0; i < 256; ++i)
            acc = fmaf(feat_s[i], __ldg(W0 + (size_t)i * 128 + j), acc);
        h1_s[j] = ftanh(acc);
    }
    __syncthreads();

    if (j < 64) {   // layer 1: 128 -> 64
        float acc = b1[j];
#pragma unroll 8
        for (int i = 0; i < 128; ++i)
            acc = fmaf(h1_s[i], __ldg(W1 + (size_t)i * 64 + j), acc);
        h2_s[j] = ftanh(acc);
    }
    __syncthreads();

    if (j < 20) {   // layer 2: 64 -> 20
        float acc = b2[j];
#pragma unroll
        for (int i = 0; i < 64; ++i)
            acc = fmaf(h2_s[i], __ldg(W2 + (size_t)i * 20 + j), acc);
        out[head * (BATCH * 20) + b * 20 + j] = acc;
    }
}

extern "C" void kernel_launch(void* const* d_in, const int* in_sizes, int n_in,
                              void* d_out, int out_size)
{
    const float* y     = (const float*)d_in[0];
    const float* u     = (const float*)d_in[1];
    const float* Wi_f  = (const float*)d_in[2];
    const float* bi_f  = (const float*)d_in[3];
    const float* Wh_f  = (const float*)d_in[4];
    const float* bhn_f = (const float*)d_in[5];
    const float* Wi_b  = (const float*)d_in[6];
    const float* bi_b  = (const float*)d_in[7];
    const float* Wh_b  = (const float*)d_in[8];
    const float* bhn_b = (const float*)d_in[9];
    const float* mW0   = (const float*)d_in[10];
    const float* mb0   = (const float*)d_in[11];
    const float* mW1   = (const float*)d_in[12];
    const float* mb1   = (const float*)d_in[13];
    const float* mW2   = (const float*)d_in[14];
    const float* mb2   = (const float*)d_in[15];
    const float* sW0   = (const float*)d_in[16];
    const float* sb0   = (const float*)d_in[17];
    const float* sW1   = (const float*)d_in[18];
    const float* sb1   = (const float*)d_in[19];
    const float* sW2   = (const float*)d_in[20];
    const float* sb2   = (const float*)d_in[21];

    gru_persist_kernel<<<BATCH * 2, 256>>>(y, u, Wi_f, bi_f, Wh_f, bhn_f,
                                           Wi_b, bi_b, Wh_b, bhn_b);
    mlp_kernel<<<BATCH * 2, 128>>>(mW0, mb0, mW1, mb1, mW2, mb2,
                                   sW0, sb0, sW1, sb1, sW2, sb2,
                                   (float*)d_out);
}

// round 15
// speedup vs baseline: 1.2499x; 1.2107x over previous
#include <cuda_runtime.h>
#include <cuda_fp16.h>
#include <math.h>

#define H      128
#define H3     384
#define BATCH  64
#define TT     2048
#define TILE   128   // time steps staged per smem chunk

// feat[b*256 + dir*128 + i] = mean over t of hidden state
__device__ float g_feat[BATCH * 2 * H];

__device__ __forceinline__ float ex2f(float x) {
    float r; asm("ex2.approx.ftz.f32 %0, %1;" : "=f"(r) : "f"(x)); return r;
}
__device__ __forceinline__ float rcpf(float x) {
    float r; asm("rcp.approx.ftz.f32 %0, %1;" : "=f"(r) : "f"(x)); return r;
}
#define L2E 1.4426950408889634f
__device__ __forceinline__ float ftanh(float x) {   // accurate path (MLP)
    return 2.0f * rcpf(1.0f + ex2f(-2.0f * L2E * x)) - 1.0f;
}

// HW tanh in fp16 (renamed: htanh collides with cuda_fp16.hpp)
__device__ __forceinline__ __half htanh_hw(__half x) {
    unsigned short xi = __half_as_ushort(x), ri;
    asm("tanh.approx.f16 %0, %1;" : "=h"(ri) : "h"(xi));
    return __ushort_as_half(ri);
}

// One persistent block per (batch, direction). 128 threads; thread i owns
// unit i COMPLETELY: all 3 gate columns, full k=128, weights as fp16x2 in
// registers (192 regs). HFMA2 dot (rt2). No role split, no partial
// exchange — ONE __syncthreads per step with ping-pong h (fp16).
__global__ void __launch_bounds__(H, 1) gru_persist_kernel(
    const float* __restrict__ y, const float* __restrict__ u,
    const float* __restrict__ Wi_f, const float* __restrict__ bi_f,
    const float* __restrict__ Wh_f, const float* __restrict__ bhn_f,
    const float* __restrict__ Wi_b, const float* __restrict__ bi_b,
    const float* __restrict__ Wh_b, const float* __restrict__ bhn_b)
{
    const int blk = blockIdx.x;        // 0..127
    const int b   = blk & (BATCH - 1);
    const int dir = blk >> 6;          // 0 = fwd, 1 = bwd
    const int i   = threadIdx.x;       // unit 0..127

    const float* Wi  = dir ? Wi_b  : Wi_f;
    const float* bi  = dir ? bi_b  : bi_f;
    const float* Wh  = dir ? Wh_b  : Wh_f;
    const float* bhn = dir ? bhn_b : bhn_f;

    // ---- register-resident recurrent weights, fp16 pairs along k ----
    __half2 wr[H / 2], wz[H / 2], wn[H / 2];
#pragma unroll
    for (int m = 0; m < H / 2; ++m) {
        const float* r0 = Wh + (size_t)(2 * m)     * H3;
        const float* r1 = Wh + (size_t)(2 * m + 1) * H3;
        wr[m] = __floats2half2_rn(r0[i],         r1[i]);
        wz[m] = __floats2half2_rn(r0[i + H],     r1[i + H]);
        wn[m] = __floats2half2_rn(r0[i + 2 * H], r1[i + 2 * H]);
    }

    // ---- shared state ----
    __shared__ __align__(16) __half h_sm[2][H];       // ping-pong hidden (fp16)
    __shared__ __align__(16) float4 yu_s[TILE * 2];   // per step: y(4)+u(4)
    __shared__ __align__(16) float4 wi4_s[2 * H3];    // Wi columns, 2 float4

    // stage Wi (thread i: its 3 columns)
#pragma unroll
    for (int g = 0; g < 3; ++g) {
        const int col = i + g * H;
        wi4_s[col]      = make_float4(Wi[0 * H3 + col], Wi[1 * H3 + col],
                                      Wi[2 * H3 + col], Wi[3 * H3 + col]);
        wi4_s[H3 + col] = make_float4(Wi[4 * H3 + col], Wi[5 * H3 + col],
                                      Wi[6 * H3 + col], Wi[7 * H3 + col]);
    }
    const float bir = bi[i], biz = bi[i + H], bin = bi[i + 2 * H];
    const __half bhn_h = __float2half(bhn[i]);
    const __half h05   = __float2half(0.5f);

    h_sm[0][i] = __float2half(0.0f);
    __syncthreads();

    float hsum = 0.0f;
    int p = 0;

    // preload chunk 0 inputs into regs
    float4 y4n, u4n;
    {
        const int tc0 = (dir ? (TT - TILE) : 0) + i;
        y4n = *(const float4*)(y + ((size_t)b * TT + tc0) * 4);
        u4n = *(const float4*)(u + ((size_t)b * TT + tc0) * 4);
    }

    const int nchunk = TT / TILE;
    for (int c = 0; c < nchunk; ++c) {
        // stage current chunk; prefetch next
        yu_s[2 * i]     = y4n;
        yu_s[2 * i + 1] = u4n;
        __syncthreads();
        if (c + 1 < nchunk) {
            const int t0n = (dir ? (TT - (c + 2) * TILE) : ((c + 1) * TILE)) + i;
            y4n = *(const float4*)(y + ((size_t)b * TT + t0n) * 4);
            u4n = *(const float4*)(u + ((size_t)b * TT + t0n) * 4);
        }

        const int tt0 = dir ? (TILE - 1) : 0;
        const int sgn = dir ? -1 : 1;

        for (int s = 0; s < TILE; ++s) {
            const int tt = tt0 + sgn * s;

            // ---- xw (fp32, independent of h; fills dot-window gaps) ----
            const float4 ya = yu_s[2 * tt];
            const float4 ub = yu_s[2 * tt + 1];
            const float4 war = wi4_s[i],          wbr = wi4_s[H3 + i];
            const float4 waz = wi4_s[i + H],      wbz = wi4_s[H3 + i + H];
            const float4 wan = wi4_s[i + 2 * H],  wbn = wi4_s[H3 + i + 2 * H];
            float xr = bir, xz = biz, xn = bin;
            xr = fmaf(ya.x, war.x, xr); xr = fmaf(ya.y, war.y, xr);
            xr = fmaf(ya.z, war.z, xr); xr = fmaf(ya.w, war.w, xr);
            xr = fmaf(ub.x, wbr.x, xr); xr = fmaf(ub.y, wbr.y, xr);
            xr = fmaf(ub.z, wbr.z, xr); xr = fmaf(ub.w, wbr.w, xr);
            xz = fmaf(ya.x, waz.x, xz); xz = fmaf(ya.y, waz.y, xz);
            xz = fmaf(ya.z, waz.z, xz); xz = fmaf(ya.w, waz.w, xz);
            xz = fmaf(ub.x, wbz.x, xz); xz = fmaf(ub.y, wbz.y, xz);
            xz = fmaf(ub.z, wbz.z, xz); xz = fmaf(ub.w, wbz.w, xz);
            xn = fmaf(ya.x, wan.x, xn); xn = fmaf(ya.y, wan.y, xn);
            xn = fmaf(ya.z, wan.z, xn); xn = fmaf(ya.w, wan.w, xn);
            xn = fmaf(ub.x, wbn.x, xn); xn = fmaf(ub.y, wbn.y, xn);
            xn = fmaf(ub.z, wbn.z, xn); xn = fmaf(ub.w, wbn.w, xn);
            const __half xr_h = __float2half(xr);
            const __half xz_h = __float2half(xz);
            const __half xn_h = __float2half(xn);

            // ---- fp16 dot: 3 gates x full k, HFMA2, 6 accumulators ----
            const uint4* hq = (const uint4*)h_sm[p];
            const __half2 z2 = __floats2half2_rn(0.0f, 0.0f);
            __half2 ar0 = z2, ar1 = z2, az0 = z2, az1 = z2, an0 = z2, an1 = z2;
#pragma unroll
            for (int q = 0; q < 16; ++q) {
                const uint4 hv = hq[q];               // broadcast LDS.128
                const __half2 h0 = *(const __half2*)&hv.x;
                const __half2 h1 = *(const __half2*)&hv.y;
                const __half2 h2 = *(const __half2*)&hv.z;
                const __half2 h3 = *(const __half2*)&hv.w;
                ar0 = __hfma2(h0, wr[4 * q + 0], ar0);
                az0 = __hfma2(h0, wz[4 * q + 0], az0);
                an0 = __hfma2(h0, wn[4 * q + 0], an0);
                ar1 = __hfma2(h1, wr[4 * q + 1], ar1);
                az1 = __hfma2(h1, wz[4 * q + 1], az1);
                an1 = __hfma2(h1, wn[4 * q + 1], an1);
                ar0 = __hfma2(h2, wr[4 * q + 2], ar0);
                az0 = __hfma2(h2, wz[4 * q + 2], az0);
                an0 = __hfma2(h2, wn[4 * q + 2], an0);
                ar1 = __hfma2(h3, wr[4 * q + 3], ar1);
                az1 = __hfma2(h3, wz[4 * q + 3], az1);
                an1 = __hfma2(h3, wn[4 * q + 3], an1);
            }
            const __half2 arv = __hadd2(ar0, ar1);
            const __half2 azv = __hadd2(az0, az1);
            const __half2 anv = __hadd2(an0, an1);
            const __half dr = __hadd(__low2half(arv), __high2half(arv));
            const __half dz = __hadd(__low2half(azv), __high2half(azv));
            const __half dn = __hadd(__low2half(anv), __high2half(anv));

            // ---- gates, all fp16 ----
            const __half hold = h_sm[p][i];
            const __half r = __hfma(h05, htanh_hw(__hmul(h05, __hadd(xr_h, dr))), h05);
            const __half z = __hfma(h05, htanh_hw(__hmul(h05, __hadd(xz_h, dz))), h05);
            const __half P   = __hadd(dn, bhn_h);
            const __half arg = __hfma(r, P, xn_h);
            const __half n   = htanh_hw(arg);
            const __half hn  = __hfma(z, __hsub(hold, n), n);   // (1-z)n + z h
            h_sm[p ^ 1][i] = hn;
            __syncthreads();                 // ONE barrier per step
            p ^= 1;
            hsum += __half2float(hn);        // fp32 accumulate, off path
        }
    }

    g_feat[b * (2 * H) + dir * H + i] = hsum * (1.0f / (float)TT);
}

// MLP heads: 256 -> 128 -> 64 -> 20, tanh, tanh, linear. (accurate tanh)
__global__ void __launch_bounds__(128) mlp_kernel(
    const float* __restrict__ mW0, const float* __restrict__ mb0,
    const float* __restrict__ mW1, const float* __restrict__ mb1,
    const float* __restrict__ mW2, const float* __restrict__ mb2,
    const float* __restrict__ sW0, const float* __restrict__ sb0,
    const float* __restrict__ sW1, const float* __restrict__ sb1,
    const float* __restrict__ sW2, const float* __restrict__ sb2,
    float* __restrict__ out)
{
    const int b    = blockIdx.x & (BATCH - 1);
    const int head = blockIdx.x >> 6;
    const int j    = threadIdx.x;

    const float* W0 = head ? sW0 : mW0;
    const float* b0 = head ? sb0 : mb0;
    const float* W1 = head ? sW1 : mW1;
    const float* b1 = head ? sb1 : mb1;
    const float* W2 = head ? sW2 : mW2;
    const float* b2 = head ? sb2 : mb2;

    __shared__ float feat_s[256];
    __shared__ float h1_s[128];
    __shared__ float h2_s[64];

    feat_s[j]       = g_feat[b * 256 + j];
    feat_s[j + 128] = g_feat[b * 256 + j + 128];
    __syncthreads();

    {   // layer 0: 256 -> 128
        float acc = b0[j];
#pragma unroll 16
        for (int i = 0; i < 256; ++i)
            acc = fmaf(feat_s[i], __ldg(W0 + (size_t)i * 128 + j), acc);
        h1_s[j] = ftanh(acc);
    }
    __syncthreads();

    if (j < 64) {   // layer 1: 128 -> 64
        float acc = b1[j];
#pragma unroll 16
        for (int i = 0; i < 128; ++i)
            acc = fmaf(h1_s[i], __ldg(W1 + (size_t)i * 64 + j), acc);
        h2_s[j] = ftanh(acc);
    }
    __syncthreads();

    if (j < 20) {   // layer 2: 64 -> 20
        float acc = b2[j];
#pragma unroll
        for (int i = 0; i < 64; ++i)
            acc = fmaf(h2_s[i], __ldg(W2 + (size_t)i * 20 + j), acc);
        out[head * (BATCH * 20) + b * 20 + j] = acc;
    }
}

extern "C" void kernel_launch(void* const* d_in, const int* in_sizes, int n_in,
                              void* d_out, int out_size)
{
    const float* y     = (const float*)d_in[0];
    const float* u     = (const float*)d_in[1];
    const float* Wi_f  = (const float*)d_in[2];
    const float* bi_f  = (const float*)d_in[3];
    const float* Wh_f  = (const float*)d_in[4];
    const float* bhn_f = (const float*)d_in[5];
    const float* Wi_b  = (const float*)d_in[6];
    const float* bi_b  = (const float*)d_in[7];
    const float* Wh_b  = (const float*)d_in[8];
    const float* bhn_b = (const float*)d_in[9];
    const float* mW0   = (const float*)d_in[10];
    const float* mb0   = (const float*)d_in[11];
    const float* mW1   = (const float*)d_in[12];
    const float* mb1   = (const float*)d_in[13];
    const float* mW2   = (const float*)d_in[14];
    const float* mb2   = (const float*)d_in[15];
    const float* sW0   = (const float*)d_in[16];
    const float* sb0   = (const float*)d_in[17];
    const float* sW1   = (const float*)d_in[18];
    const float* sb1   = (const float*)d_in[19];
    const float* sW2   = (const float*)d_in[20];
    const float* sb2   = (const float*)d_in[21];

    gru_persist_kernel<<<BATCH * 2, H>>>(y, u, Wi_f, bi_f, Wh_f, bhn_f,
                                         Wi_b, bi_b, Wh_b, bhn_b);
    mlp_kernel<<<BATCH * 2, 128>>>(mW0, mb0, mW1, mb1, mW2, mb2,
                                   sW0, sb0, sW1, sb1, sW2, sb2,
                                   (float*)d_out);
}